// round 3
// baseline (speedup 1.0000x reference)
#include <cuda_runtime.h>
#include <cstdint>

#define Bsz   128
#define TIN   240
#define TOUT  30
#define Dd    128
#define Hh    256
#define G3    768
#define ENC_L (TIN*Bsz)   /* 30720 */
#define DEC_L (TOUT*Bsz)  /* 3840  */

// scratch: precomputed gi = x_seq @ Wih^T + (bih + bhh[r,z gates])
__device__ float g_gi_enc[(size_t)ENC_L * G3];   // ~94 MB
__device__ float g_gi_dec[(size_t)DEC_L * G3];   // ~12 MB

typedef unsigned long long u64t;

__device__ __forceinline__ u64t ffma2(u64t a, u64t b, u64t c) {
    u64t d;
    asm("fma.rn.f32x2 %0, %1, %2, %3;" : "=l"(d) : "l"(a), "l"(b), "l"(c));
    return d;
}
__device__ __forceinline__ u64t fadd2(u64t a, u64t b) {
    u64t d;
    asm("add.rn.f32x2 %0, %1, %2;" : "=l"(d) : "l"(a), "l"(b));
    return d;
}
__device__ __forceinline__ float sumpair(u64t a) {
    float x, y;
    asm("mov.b64 {%0, %1}, %2;" : "=f"(x), "=f"(y) : "l"(a));
    return x + y;
}
__device__ __forceinline__ float tanh_fast(float x) {
    float y;
    asm("tanh.approx.f32 %0, %1;" : "=f"(y) : "f"(x));
    return y;
}
__device__ __forceinline__ float sigmoid_fast(float x) {
    return fmaf(0.5f, tanh_fast(0.5f * x), 0.5f);
}
__device__ __forceinline__ uint32_t mapa_u32(uint32_t a, uint32_t rank) {
    uint32_t d;
    asm("mapa.shared::cluster.u32 %0, %1, %2;" : "=r"(d) : "r"(a), "r"(rank));
    return d;
}
__device__ __forceinline__ void mbar_init(uint32_t a, uint32_t cnt) {
    asm volatile("mbarrier.init.shared.b64 [%0], %1;" :: "r"(a), "r"(cnt) : "memory");
}
__device__ __forceinline__ void mbar_arrive_remote(uint32_t ra) {
    asm volatile("mbarrier.arrive.release.cluster.shared::cluster.b64 _, [%0];"
                 :: "r"(ra) : "memory");
}
__device__ __forceinline__ void mbar_wait(uint32_t a, uint32_t parity) {
    asm volatile(
        "{\n\t.reg .pred P;\n\t"
        "WL%=:\n\t"
        "mbarrier.try_wait.parity.acquire.cluster.shared::cta.b64 P, [%0], %1, 0x989680;\n\t"
        "@P bra.uni WD%=;\n\t"
        "bra.uni WL%=;\n\t"
        "WD%=:\n\t}"
        :: "r"(a), "r"(parity) : "memory");
}
__device__ __forceinline__ void st_remote_f32(uint32_t ra, float v) {
    asm volatile("st.shared::cluster.f32 [%0], %1;" :: "r"(ra), "f"(v) : "memory");
}

// ===================== Kernel 1: gi GEMM =====================
// Gi[s, c] = sum_d X[b, t, d] * Wih[c, d] + bih[c] + (c<512 ? bhh[c] : 0)
//   s = t*128 + b ; t = (s>>7)*tstride
__global__ void __launch_bounds__(256) gi_gemm(
    const float* __restrict__ X, const float* __restrict__ Wih,
    const float* __restrict__ bih, const float* __restrict__ bhh,
    int tstride, int which)
{
    float* __restrict__ Gi = which ? g_gi_dec : g_gi_enc;
    __shared__ float As[64][65];
    __shared__ float Bs[64][65];
    const int tid = threadIdx.x;
    const int tx = tid & 15, ty = tid >> 4;
    const int row0 = blockIdx.y * 64, col0 = blockIdx.x * 64;
    float acc[4][4];
#pragma unroll
    for (int p = 0; p < 4; p++)
#pragma unroll
        for (int q = 0; q < 4; q++) acc[p][q] = 0.f;

    for (int kk = 0; kk < 128; kk += 64) {
#pragma unroll
        for (int i = 0; i < 16; i++) {
            int e = i * 256 + tid;
            int r = e >> 6, k = e & 63;
            int s = row0 + r;
            int b = s & 127, t = (s >> 7) * tstride;
            As[r][k] = X[((size_t)b * TIN + t) * 128 + kk + k];
        }
#pragma unroll
        for (int i = 0; i < 16; i++) {
            int e = i * 256 + tid;
            int c = e >> 6, k = e & 63;
            Bs[k][c] = Wih[(size_t)(col0 + c) * 128 + kk + k];
        }
        __syncthreads();
#pragma unroll 8
        for (int k = 0; k < 64; k++) {
            float a[4], b[4];
#pragma unroll
            for (int q = 0; q < 4; q++) a[q] = As[ty * 4 + q][k];
#pragma unroll
            for (int q = 0; q < 4; q++) b[q] = Bs[k][tx * 4 + q];
#pragma unroll
            for (int p = 0; p < 4; p++)
#pragma unroll
                for (int q = 0; q < 4; q++) acc[p][q] = fmaf(a[p], b[q], acc[p][q]);
        }
        __syncthreads();
    }
#pragma unroll
    for (int p = 0; p < 4; p++) {
        int s = row0 + ty * 4 + p;
#pragma unroll
        for (int q = 0; q < 4; q++) {
            int c = col0 + tx * 4 + q;
            float bias = bih[c] + (c < 512 ? bhh[c] : 0.f);
            Gi[(size_t)s * G3 + c] = acc[p][q] + bias;
        }
    }
}

// ===================== Kernel 2: sequential GRU scan =====================
// grid = 16 CTAs = 2 clusters of 8 (cluster 0: encoder, cluster 1: decoder).
// Each CTA owns 96 of the 768 gh-rows (32 per gate), weights in registers.
// Per step: reg-weight matvec (f32x2 FMA) + 2 shfl reduce -> warp 0 computes
// 32 h_new, pushes to all 8 CTAs via DSMEM st.shared::cluster, signals via
// mbarrier.arrive.release.cluster (count=8, double-buffered). No cluster
// barrier inside the loop.
__global__ void __launch_bounds__(768, 1) __cluster_dims__(8, 1, 1)
gru_scan(const float* __restrict__ Whh_e, const float* __restrict__ bhh_e,
         const float* __restrict__ Whh_d, const float* __restrict__ bhh_d,
         float* __restrict__ out)
{
    __shared__ __align__(16) float hbuf[2][Hh];    // double-buffered h
    __shared__ __align__(16) float stage[2][96];   // 2 partials per gh row
    __shared__ __align__(8)  unsigned long long mb[2];

    const int which = blockIdx.x >> 3;      // 0 = encoder, 1 = decoder
    const int crank = blockIdx.x & 7;       // rank within cluster
    const float* __restrict__ Whh = which ? Whh_d : Whh_e;
    const float* __restrict__ bhh = which ? bhh_d : bhh_e;
    const float* __restrict__ gi  = which ? g_gi_dec : g_gi_enc;
    float* __restrict__ out_enc = out;                    // (240, 256)
    float* __restrict__ out_dec = out + (size_t)TIN * Hh; // (128, 30, 256)
    const int L = which ? DEC_L : ENC_L;

    const int tid = threadIdx.x;
    const int w = tid >> 5, lane = tid & 31;
    const int kc = lane >> 2;        // k-chunk 0..7 (32 floats each)
    const int rl = lane & 3;         // row-in-warp 0..3
    const int l  = 4 * w + rl;       // local row 0..95
    const int g  = l >> 5, j = l & 31;
    const int R  = g * 256 + crank * 32 + j;   // global gh row

    // weight slice into registers: Whh[R, kc*32 .. kc*32+32)
    u64t wreg[16];
    {
        const ulonglong2* wp =
            (const ulonglong2*)(Whh + (size_t)R * Hh + kc * 32);
#pragma unroll
        for (int i = 0; i < 8; i++) {
            ulonglong2 v = wp[i];
            wreg[2 * i]     = v.x;
            wreg[2 * i + 1] = v.y;
        }
    }

    const uint32_t mb_base = (uint32_t)__cvta_generic_to_shared(&mb[0]);
    const uint32_t hb_base = (uint32_t)__cvta_generic_to_shared(&hbuf[0][0]);

    // gate-warp (warp 0) private state
    float bhn = 0.f, hprev = 0.f;
    const float* gp = gi + crank * 32 + lane;
    float g0a = 0.f, g0b = 0.f, g0c = 0.f;   // gi for step s
    float g1a = 0.f, g1b = 0.f, g1c = 0.f;   // gi for step s+1
    if (w == 0) {
        bhn = bhh[512 + crank * 32 + lane];
        g0a = __ldg(gp);       g0b = __ldg(gp + 256);       g0c = __ldg(gp + 512);
        const float* q1 = gp + G3;
        g1a = __ldg(q1);       g1b = __ldg(q1 + 256);       g1c = __ldg(q1 + 512);
    }

    if (tid < Hh) { hbuf[0][tid] = 0.f; }
    if (tid == 0) { mbar_init(mb_base, 8); mbar_init(mb_base + 8, 8); }
    __syncthreads();

    // all CTAs' mbarriers initialized + hbuf[0] zeroed before any traffic
    asm volatile("barrier.cluster.arrive.aligned;" ::: "memory");
    asm volatile("barrier.cluster.wait.aligned;" ::: "memory");

    // pre-complete phase 0 of mb[0]: one arrive per (src CTA -> dst CTA) pair
    if (tid == 0) {
#pragma unroll
        for (int t = 0; t < 8; t++) mbar_arrive_remote(mapa_u32(mb_base, t));
    }

    for (int s = 0; s < L; s++) {
        const int cur = s & 1, nxt = cur ^ 1;

        // prefetch gi for step s+2 (independent of h)
        float ta = 0.f, tb = 0.f, tc = 0.f;
        if (w == 0 && s + 2 < L) {
            const float* q = gp + (size_t)(s + 2) * G3;
            ta = __ldg(q); tb = __ldg(q + 256); tc = __ldg(q + 512);
        }

        // wait for h_s fully delivered into hbuf[cur]
        mbar_wait(mb_base + 8u * (uint32_t)cur, (uint32_t)((s >> 1) & 1));

        // matvec partial: dot(Whh[R, kc*32..+32), h[kc*32..+32))
        const ulonglong2* hp = (const ulonglong2*)&hbuf[cur][kc * 32];
        u64t a0 = 0ull, a1 = 0ull, a2 = 0ull, a3 = 0ull;
#pragma unroll
        for (int i = 0; i < 4; i++) {
            ulonglong2 h0 = hp[2 * i];
            ulonglong2 h1 = hp[2 * i + 1];
            a0 = ffma2(wreg[4 * i + 0], h0.x, a0);
            a1 = ffma2(wreg[4 * i + 1], h0.y, a1);
            a2 = ffma2(wreg[4 * i + 2], h1.x, a2);
            a3 = ffma2(wreg[4 * i + 3], h1.y, a3);
        }
        float v = sumpair(fadd2(fadd2(a0, a1), fadd2(a2, a3)));
        // reduce kc bits 0,1 (lanes xor 4, 8); leaves halves kc<4 / kc>=4
        v += __shfl_xor_sync(0xffffffffu, v, 4);
        v += __shfl_xor_sync(0xffffffffu, v, 8);
        if ((lane & 12) == 0) stage[lane >> 4][l] = v;
        __syncthreads();

        if (w == 0) {
            const float sr = stage[0][lane]      + stage[1][lane];
            const float sz = stage[0][32 + lane] + stage[1][32 + lane];
            const float sn = stage[0][64 + lane] + stage[1][64 + lane] + bhn;
            const float r = sigmoid_fast(g0a + sr);
            const float z = sigmoid_fast(g0b + sz);
            const float n = tanh_fast(g0c + r * sn);
            const float hnew = n + z * (hprev - n);
            hprev = hnew;

            if (s + 1 < L) {
                // push my 32-chunk of h_{s+1} to all 8 CTAs (buffer nxt)
                const uint32_t laddr =
                    hb_base + (uint32_t)((nxt * Hh + crank * 32 + lane) * 4);
#pragma unroll
                for (int t = 0; t < 8; t++)
                    st_remote_f32(mapa_u32(laddr, t), hnew);
                __syncwarp();
                if (lane == 0) {
                    const uint32_t mbn = mb_base + 8u * (uint32_t)nxt;
#pragma unroll
                    for (int t = 0; t < 8; t++)
                        mbar_arrive_remote(mapa_u32(mbn, t));
                }
            }

            if (which) {
                const int b = s & 127, t = s >> 7;
                out_dec[((size_t)b * TOUT + t) * Hh + crank * 32 + lane] = hnew;
            } else if ((s & 127) == 127) {
                const int t = s >> 7;
                out_enc[(size_t)t * Hh + crank * 32 + lane] = hnew;
            }
            g0a = g1a; g0b = g1b; g0c = g1c;
            g1a = ta;  g1b = tb;  g1c = tc;
        }
    }

    // don't exit while peers' DSMEM stores targeting this CTA are in flight
    asm volatile("barrier.cluster.arrive.aligned;" ::: "memory");
    asm volatile("barrier.cluster.wait.aligned;" ::: "memory");
}

extern "C" void kernel_launch(void* const* d_in, const int* in_sizes, int n_in,
                              void* d_out, int out_size) {
    const float* x        = (const float*)d_in[0];
    const float* W_ih_enc = (const float*)d_in[1];
    const float* W_hh_enc = (const float*)d_in[2];
    const float* b_ih_enc = (const float*)d_in[3];
    const float* b_hh_enc = (const float*)d_in[4];
    const float* W_ih_dec = (const float*)d_in[5];
    const float* W_hh_dec = (const float*)d_in[6];
    const float* b_ih_dec = (const float*)d_in[7];
    const float* b_hh_dec = (const float*)d_in[8];
    float* out = (float*)d_out;

    // 1) precompute input gates (encoder: stride 1, decoder: stride 8)
    gi_gemm<<<dim3(G3 / 64, ENC_L / 64), 256>>>(
        x, W_ih_enc, b_ih_enc, b_hh_enc, 1, 0);
    gi_gemm<<<dim3(G3 / 64, DEC_L / 64), 256>>>(
        x, W_ih_dec, b_ih_dec, b_hh_dec, 8, 1);

    // 2) sequential scans: 2 clusters of 8 CTAs (encoder + decoder concurrent)
    gru_scan<<<16, 768>>>(W_hh_enc, b_hh_enc, W_hh_dec, b_hh_dec, out);
}

// round 4
// speedup vs baseline: 6.4885x; 6.4885x over previous
#include <cuda_runtime.h>
#include <cstdint>

#define Bsz   128
#define TIN   240
#define TOUT  30
#define Dd    128
#define Hh    256
#define G3    768
#define ENC_L (TIN*Bsz)   /* 30720 */
#define DEC_L (TOUT*Bsz)  /* 3840  */
#define ENC_YBLK (ENC_L/64)   /* 480 */
#define DEC_YBLK (DEC_L/64)   /* 60  */

// scratch: precomputed gi = x_seq @ Wih^T + (bih + bhh[r,z gates])
__device__ float g_gi_enc[(size_t)ENC_L * G3];   // ~94 MB
__device__ float g_gi_dec[(size_t)DEC_L * G3];   // ~12 MB

typedef unsigned long long u64t;

__device__ __forceinline__ u64t ffma2(u64t a, u64t b, u64t c) {
    u64t d;
    asm("fma.rn.f32x2 %0, %1, %2, %3;" : "=l"(d) : "l"(a), "l"(b), "l"(c));
    return d;
}
__device__ __forceinline__ u64t fadd2(u64t a, u64t b) {
    u64t d;
    asm("add.rn.f32x2 %0, %1, %2;" : "=l"(d) : "l"(a), "l"(b));
    return d;
}
__device__ __forceinline__ float sumpair(u64t a) {
    float x, y;
    asm("mov.b64 {%0, %1}, %2;" : "=f"(x), "=f"(y) : "l"(a));
    return x + y;
}
__device__ __forceinline__ float tanh_fast(float x) {
    float y;
    asm("tanh.approx.f32 %0, %1;" : "=f"(y) : "f"(x));
    return y;
}
__device__ __forceinline__ float sigmoid_fast(float x) {
    return fmaf(0.5f, tanh_fast(0.5f * x), 0.5f);
}
__device__ __forceinline__ uint32_t mapa_u32(uint32_t a, uint32_t rank) {
    uint32_t d;
    asm("mapa.shared::cluster.u32 %0, %1, %2;" : "=r"(d) : "r"(a), "r"(rank));
    return d;
}
__device__ __forceinline__ void mbar_init(uint32_t a, uint32_t cnt) {
    asm volatile("mbarrier.init.shared.b64 [%0], %1;" :: "r"(a), "r"(cnt) : "memory");
}
__device__ __forceinline__ void mbar_expect_tx(uint32_t a, uint32_t bytes) {
    asm volatile("mbarrier.arrive.expect_tx.shared.b64 _, [%0], %1;"
                 :: "r"(a), "r"(bytes) : "memory");
}
// local poll, CTA-scope acquire (NO cluster-scope fence in the loop)
__device__ __forceinline__ void mbar_wait(uint32_t a, uint32_t parity) {
    asm volatile(
        "{\n\t.reg .pred P;\n\t"
        "WL%=:\n\t"
        "mbarrier.try_wait.parity.acquire.cta.shared::cta.b64 P, [%0], %1, 0x989680;\n\t"
        "@P bra.uni WD%=;\n\t"
        "bra.uni WL%=;\n\t"
        "WD%=:\n\t}"
        :: "r"(a), "r"(parity) : "memory");
}
// store 16B to a cluster peer's smem; completion feeds peer's mbarrier tx count
__device__ __forceinline__ void st_async_v4(uint32_t ra, float4 v, uint32_t rmbar) {
    asm volatile(
        "st.async.weak.shared::cluster.mbarrier::complete_tx::bytes.v4.f32 "
        "[%0], {%1, %2, %3, %4}, [%5];"
        :: "r"(ra), "f"(v.x), "f"(v.y), "f"(v.z), "f"(v.w), "r"(rmbar) : "memory");
}

// ===================== Kernel 1: gi GEMM (enc + dec fused) =====================
__global__ void __launch_bounds__(256) gi_gemm(
    const float* __restrict__ X,
    const float* __restrict__ Wih_e, const float* __restrict__ bih_e,
    const float* __restrict__ bhh_e,
    const float* __restrict__ Wih_d, const float* __restrict__ bih_d,
    const float* __restrict__ bhh_d)
{
    const int by = blockIdx.y;
    const int which = (by >= ENC_YBLK);
    const int row0 = (which ? (by - ENC_YBLK) : by) * 64;
    const int tstride = which ? 8 : 1;
    const float* __restrict__ Wih = which ? Wih_d : Wih_e;
    const float* __restrict__ bih = which ? bih_d : bih_e;
    const float* __restrict__ bhh = which ? bhh_d : bhh_e;
    float* __restrict__ Gi = which ? g_gi_dec : g_gi_enc;

    __shared__ float As[64][65];
    __shared__ float Bs[64][65];
    const int tid = threadIdx.x;
    const int tx = tid & 15, ty = tid >> 4;
    const int col0 = blockIdx.x * 64;
    float acc[4][4];
#pragma unroll
    for (int p = 0; p < 4; p++)
#pragma unroll
        for (int q = 0; q < 4; q++) acc[p][q] = 0.f;

    for (int kk = 0; kk < 128; kk += 64) {
#pragma unroll
        for (int i = 0; i < 16; i++) {
            int e = i * 256 + tid;
            int r = e >> 6, k = e & 63;
            int s = row0 + r;
            int b = s & 127, t = (s >> 7) * tstride;
            As[r][k] = X[((size_t)b * TIN + t) * 128 + kk + k];
        }
#pragma unroll
        for (int i = 0; i < 16; i++) {
            int e = i * 256 + tid;
            int c = e >> 6, k = e & 63;
            Bs[k][c] = Wih[(size_t)(col0 + c) * 128 + kk + k];
        }
        __syncthreads();
#pragma unroll 8
        for (int k = 0; k < 64; k++) {
            float a[4], b[4];
#pragma unroll
            for (int q = 0; q < 4; q++) a[q] = As[ty * 4 + q][k];
#pragma unroll
            for (int q = 0; q < 4; q++) b[q] = Bs[k][tx * 4 + q];
#pragma unroll
            for (int p = 0; p < 4; p++)
#pragma unroll
                for (int q = 0; q < 4; q++) acc[p][q] = fmaf(a[p], b[q], acc[p][q]);
        }
        __syncthreads();
    }
#pragma unroll
    for (int p = 0; p < 4; p++) {
        int s = row0 + ty * 4 + p;
#pragma unroll
        for (int q = 0; q < 4; q++) {
            int c = col0 + tx * 4 + q;
            float bias = bih[c] + (c < 512 ? bhh[c] : 0.f);
            Gi[(size_t)s * G3 + c] = acc[p][q] + bias;
        }
    }
}

// ===================== Kernel 2: sequential GRU scan =====================
// 2 clusters of 8 CTAs (cluster 0: encoder, cluster 1: decoder). Each CTA owns
// h-chunk [crank*32, +32): 96 gh rows, weights in registers. Per step:
// reg matvec (rotated conflict-free LDS) + 2 shfl + stage -> warp 0 gates ->
// st.async.v4 push of h chunk to all 8 CTAs, completion via mbarrier tx bytes.
__global__ void __launch_bounds__(768, 1) __cluster_dims__(8, 1, 1)
gru_scan(const float* __restrict__ Whh_e, const float* __restrict__ bhh_e,
         const float* __restrict__ Whh_d, const float* __restrict__ bhh_d,
         float* __restrict__ out)
{
    __shared__ __align__(16) float hbuf[2][Hh];    // double-buffered h
    __shared__ __align__(16) float stage[2][100];  // 2 partials per gh row (padded)
    __shared__ __align__(16) float gsc[32];        // gate-warp pack buffer
    __shared__ __align__(8)  unsigned long long mb[2];

    const int which = blockIdx.x >> 3;      // 0 = encoder, 1 = decoder
    const int crank = blockIdx.x & 7;       // rank within cluster
    const float* __restrict__ Whh = which ? Whh_d : Whh_e;
    const float* __restrict__ bhh = which ? bhh_d : bhh_e;
    const float* __restrict__ gi  = which ? g_gi_dec : g_gi_enc;
    float* __restrict__ out_enc = out;                    // (240, 256)
    float* __restrict__ out_dec = out + (size_t)TIN * Hh; // (128, 30, 256)
    const int L = which ? DEC_L : ENC_L;

    const int tid = threadIdx.x;
    const int w = tid >> 5, lane = tid & 31;
    const int kc = lane >> 2;        // k-chunk 0..7 (32 floats each)
    const int rl = lane & 3;         // row-in-group
    const int l  = 4 * w + rl;       // local row 0..95
    const int g  = l >> 5, j = l & 31;
    const int R  = g * 256 + crank * 32 + j;   // global gh row

    // weight slice in registers, stored in ROTATED subchunk order so that the
    // matching rotated h reads are smem-bank-conflict-free across the 8 kc
    // groups of the warp.
    u64t wreg[16];
    int rot[8];
    {
        const ulonglong2* wp =
            (const ulonglong2*)(Whh + (size_t)R * Hh + kc * 32);
#pragma unroll
        for (int i = 0; i < 8; i++) {
            const int c = (i + kc) & 7;
            ulonglong2 v = wp[c];
            wreg[2 * i]     = v.x;
            wreg[2 * i + 1] = v.y;
            rot[i] = c * 16;       // byte offset of 16B subchunk c
        }
    }

    const uint32_t mb_base = (uint32_t)__cvta_generic_to_shared(&mb[0]);
    const uint32_t hb_base = (uint32_t)__cvta_generic_to_shared(&hbuf[0][0]);

    // gate-warp (warp 0) private state
    float bhn = 0.f, hprev = 0.f;
    const float* gp = gi + crank * 32 + lane;
    float g0a = 0.f, g0b = 0.f, g0c = 0.f;   // gi for step s
    float g1a = 0.f, g1b = 0.f, g1c = 0.f;   // gi for step s+1
    if (w == 0) {
        bhn = bhh[512 + crank * 32 + lane];
        g0a = __ldg(gp);     g0b = __ldg(gp + 256);     g0c = __ldg(gp + 512);
        const float* q1 = gp + G3;
        g1a = __ldg(q1);     g1b = __ldg(q1 + 256);     g1c = __ldg(q1 + 512);
    }

    if (tid < Hh) hbuf[0][tid] = 0.f;
    if (tid == 0) {
        mbar_init(mb_base, 1);
        mbar_init(mb_base + 8, 1);
        // arm phase 0 of both barriers (h_1 -> mb[1]@s=1, h_2 -> mb[0]@s=2)
        mbar_expect_tx(mb_base, 1024);
        mbar_expect_tx(mb_base + 8, 1024);
        asm volatile("fence.mbarrier_init.release.cluster;" ::: "memory");
    }
    __syncthreads();
    // all CTAs' barriers initialized+armed before any st.async traffic
    asm volatile("barrier.cluster.arrive.aligned;" ::: "memory");
    asm volatile("barrier.cluster.wait.aligned;" ::: "memory");

    for (int s = 0; s < L; s++) {
        const int cur = s & 1, nxt = cur ^ 1;

        // prefetch gi for step s+2 (independent of h)
        float ta = 0.f, tb = 0.f, tc = 0.f;
        if (w == 0 && s + 2 < L) {
            const float* q = gp + (size_t)(s + 2) * G3;
            ta = __ldg(q); tb = __ldg(q + 256); tc = __ldg(q + 512);
        }

        if (s > 0) {
            // wait for the 1024 tx bytes of h_s into hbuf[cur]
            const uint32_t a = mb_base + 8u * (uint32_t)cur;
            mbar_wait(a, (uint32_t)(((s >> 1) + (cur ^ 1)) & 1));
            // re-arm this barrier for its next phase (used at step s+2);
            // ordered before our own pushes by the stage __syncthreads.
            if (tid == 0) mbar_expect_tx(a, 1024);
        }

        // matvec partial: dot(Whh[R, kc*32..+32), h[kc*32..+32)), rotated order
        const char* hbase = (const char*)&hbuf[cur][kc * 32];
        u64t p0 = 0ull, p1 = 0ull, p2 = 0ull, p3 = 0ull;
#pragma unroll
        for (int i = 0; i < 8; i++) {
            ulonglong2 hv = *(const ulonglong2*)(hbase + rot[i]);
            if (i & 1) {
                p2 = ffma2(wreg[2 * i],     hv.x, p2);
                p3 = ffma2(wreg[2 * i + 1], hv.y, p3);
            } else {
                p0 = ffma2(wreg[2 * i],     hv.x, p0);
                p1 = ffma2(wreg[2 * i + 1], hv.y, p1);
            }
        }
        float v = sumpair(fadd2(fadd2(p0, p1), fadd2(p2, p3)));
        // reduce over kc bits 0,1 (lane xor 4, 8); halves go to stage[0/1]
        v += __shfl_xor_sync(0xffffffffu, v, 4);
        v += __shfl_xor_sync(0xffffffffu, v, 8);
        if ((lane & 12) == 0) stage[lane >> 4][l] = v;
        __syncthreads();

        if (w == 0) {
            const float sr = stage[0][lane]      + stage[1][lane];
            const float sz = stage[0][32 + lane] + stage[1][32 + lane];
            const float sn = stage[0][64 + lane] + stage[1][64 + lane] + bhn;
            const float r = sigmoid_fast(g0a + sr);
            const float z = sigmoid_fast(g0b + sz);
            const float n = tanh_fast(g0c + r * sn);
            const float hnew = n + z * (hprev - n);
            hprev = hnew;

            if (s + 1 < L) {
                gsc[lane] = hnew;
                __syncwarp();
                // pack: each lane ships 2x16B of this CTA's 128B chunk to one rank
                const uint32_t rank = (uint32_t)(lane >> 2);
                const int sub = lane & 3;
                const float4 va = ((const float4*)gsc)[sub];
                const float4 vb = ((const float4*)gsc)[sub + 4];
                const uint32_t dst =
                    hb_base + (uint32_t)((nxt * Hh + crank * 32) * 4);
                const uint32_t rm =
                    mapa_u32(mb_base + 8u * (uint32_t)nxt, rank);
                st_async_v4(mapa_u32(dst + sub * 16, rank), va, rm);
                st_async_v4(mapa_u32(dst + (sub + 4) * 16, rank), vb, rm);
            }

            if (which) {
                const int b = s & 127, t = s >> 7;
                out_dec[((size_t)b * TOUT + t) * Hh + crank * 32 + lane] = hnew;
            } else if ((s & 127) == 127) {
                const int t = s >> 7;
                out_enc[(size_t)t * Hh + crank * 32 + lane] = hnew;
            }
            g0a = g1a; g0b = g1b; g0c = g1c;
            g1a = ta;  g1b = tb;  g1c = tc;
        }
    }

    // don't exit while peers' st.async traffic targeting this CTA is in flight
    asm volatile("barrier.cluster.arrive.aligned;" ::: "memory");
    asm volatile("barrier.cluster.wait.aligned;" ::: "memory");
}

extern "C" void kernel_launch(void* const* d_in, const int* in_sizes, int n_in,
                              void* d_out, int out_size) {
    const float* x        = (const float*)d_in[0];
    const float* W_ih_enc = (const float*)d_in[1];
    const float* W_hh_enc = (const float*)d_in[2];
    const float* b_ih_enc = (const float*)d_in[3];
    const float* b_hh_enc = (const float*)d_in[4];
    const float* W_ih_dec = (const float*)d_in[5];
    const float* W_hh_dec = (const float*)d_in[6];
    const float* b_ih_dec = (const float*)d_in[7];
    const float* b_hh_dec = (const float*)d_in[8];
    float* out = (float*)d_out;

    // 1) precompute input gates (encoder stride 1 + decoder stride 8, fused)
    gi_gemm<<<dim3(G3 / 64, ENC_YBLK + DEC_YBLK), 256>>>(
        x, W_ih_enc, b_ih_enc, b_hh_enc, W_ih_dec, b_ih_dec, b_hh_dec);

    // 2) sequential scans: 2 clusters of 8 CTAs (encoder + decoder concurrent)
    gru_scan<<<16, 768>>>(W_hh_enc, b_hh_enc, W_hh_dec, b_hh_dec, out);
}

// round 5
// speedup vs baseline: 7.4081x; 1.1417x over previous
#include <cuda_runtime.h>
#include <cstdint>

#define Bsz   128
#define TIN   240
#define TOUT  30
#define Dd    128
#define Hh    256
#define G3    768
#define ENC_L (TIN*Bsz)   /* 30720 */
#define DEC_L (TOUT*Bsz)  /* 3840  */
#define ENC_YBLK (ENC_L/64)   /* 480 */
#define DEC_YBLK (DEC_L/64)   /* 60  */

// scratch: precomputed gi = x_seq @ Wih^T + (bih + bhh[r,z gates])
__device__ float g_gi_enc[(size_t)ENC_L * G3];   // ~94 MB
__device__ float g_gi_dec[(size_t)DEC_L * G3];   // ~12 MB

typedef unsigned long long u64t;

__device__ __forceinline__ u64t ffma2(u64t a, u64t b, u64t c) {
    u64t d;
    asm("fma.rn.f32x2 %0, %1, %2, %3;" : "=l"(d) : "l"(a), "l"(b), "l"(c));
    return d;
}
__device__ __forceinline__ u64t fadd2(u64t a, u64t b) {
    u64t d;
    asm("add.rn.f32x2 %0, %1, %2;" : "=l"(d) : "l"(a), "l"(b));
    return d;
}
__device__ __forceinline__ float sumpair(u64t a) {
    float x, y;
    asm("mov.b64 {%0, %1}, %2;" : "=f"(x), "=f"(y) : "l"(a));
    return x + y;
}
__device__ __forceinline__ float tanh_fast(float x) {
    float y;
    asm("tanh.approx.f32 %0, %1;" : "=f"(y) : "f"(x));
    return y;
}
__device__ __forceinline__ float sigmoid_fast(float x) {
    return fmaf(0.5f, tanh_fast(0.5f * x), 0.5f);
}
__device__ __forceinline__ uint32_t mapa_u32(uint32_t a, uint32_t rank) {
    uint32_t d;
    asm("mapa.shared::cluster.u32 %0, %1, %2;" : "=r"(d) : "r"(a), "r"(rank));
    return d;
}
__device__ __forceinline__ void mbar_init(uint32_t a, uint32_t cnt) {
    asm volatile("mbarrier.init.shared.b64 [%0], %1;" :: "r"(a), "r"(cnt) : "memory");
}
__device__ __forceinline__ void mbar_expect_tx(uint32_t a, uint32_t bytes) {
    asm volatile("mbarrier.arrive.expect_tx.shared.b64 _, [%0], %1;"
                 :: "r"(a), "r"(bytes) : "memory");
}
// local poll, CTA-scope acquire (NO cluster-scope fence in the loop)
__device__ __forceinline__ void mbar_wait(uint32_t a, uint32_t parity) {
    asm volatile(
        "{\n\t.reg .pred P;\n\t"
        "WL%=:\n\t"
        "mbarrier.try_wait.parity.acquire.cta.shared::cta.b64 P, [%0], %1, 0x989680;\n\t"
        "@P bra.uni WD%=;\n\t"
        "bra.uni WL%=;\n\t"
        "WD%=:\n\t}"
        :: "r"(a), "r"(parity) : "memory");
}
// store 16B to a cluster peer's smem; completion feeds peer's mbarrier tx count
__device__ __forceinline__ void st_async_v4(uint32_t ra, float4 v, uint32_t rmbar) {
    asm volatile(
        "st.async.weak.shared::cluster.mbarrier::complete_tx::bytes.v4.f32 "
        "[%0], {%1, %2, %3, %4}, [%5];"
        :: "r"(ra), "f"(v.x), "f"(v.y), "f"(v.z), "f"(v.w), "r"(rmbar) : "memory");
}

// ===================== Kernel 1: gi GEMM (enc + dec fused) =====================
__global__ void __launch_bounds__(256) gi_gemm(
    const float* __restrict__ X,
    const float* __restrict__ Wih_e, const float* __restrict__ bih_e,
    const float* __restrict__ bhh_e,
    const float* __restrict__ Wih_d, const float* __restrict__ bih_d,
    const float* __restrict__ bhh_d)
{
    const int by = blockIdx.y;
    const int which = (by >= ENC_YBLK);
    const int row0 = (which ? (by - ENC_YBLK) : by) * 64;
    const int tstride = which ? 8 : 1;
    const float* __restrict__ Wih = which ? Wih_d : Wih_e;
    const float* __restrict__ bih = which ? bih_d : bih_e;
    const float* __restrict__ bhh = which ? bhh_d : bhh_e;
    float* __restrict__ Gi = which ? g_gi_dec : g_gi_enc;

    __shared__ float As[64][65];
    __shared__ float Bs[64][65];
    const int tid = threadIdx.x;
    const int tx = tid & 15, ty = tid >> 4;
    const int col0 = blockIdx.x * 64;
    float acc[4][4];
#pragma unroll
    for (int p = 0; p < 4; p++)
#pragma unroll
        for (int q = 0; q < 4; q++) acc[p][q] = 0.f;

    for (int kk = 0; kk < 128; kk += 64) {
#pragma unroll
        for (int i = 0; i < 16; i++) {
            int e = i * 256 + tid;
            int r = e >> 6, k = e & 63;
            int s = row0 + r;
            int b = s & 127, t = (s >> 7) * tstride;
            As[r][k] = X[((size_t)b * TIN + t) * 128 + kk + k];
        }
#pragma unroll
        for (int i = 0; i < 16; i++) {
            int e = i * 256 + tid;
            int c = e >> 6, k = e & 63;
            Bs[k][c] = Wih[(size_t)(col0 + c) * 128 + kk + k];
        }
        __syncthreads();
#pragma unroll 8
        for (int k = 0; k < 64; k++) {
            float a[4], b[4];
#pragma unroll
            for (int q = 0; q < 4; q++) a[q] = As[ty * 4 + q][k];
#pragma unroll
            for (int q = 0; q < 4; q++) b[q] = Bs[k][tx * 4 + q];
#pragma unroll
            for (int p = 0; p < 4; p++)
#pragma unroll
                for (int q = 0; q < 4; q++) acc[p][q] = fmaf(a[p], b[q], acc[p][q]);
        }
        __syncthreads();
    }
#pragma unroll
    for (int p = 0; p < 4; p++) {
        int s = row0 + ty * 4 + p;
#pragma unroll
        for (int q = 0; q < 4; q++) {
            int c = col0 + tx * 4 + q;
            float bias = bih[c] + (c < 512 ? bhh[c] : 0.f);
            Gi[(size_t)s * G3 + c] = acc[p][q] + bias;
        }
    }
}

// ===================== Kernel 2: sequential GRU scan =====================
// 2 clusters of 8 CTAs (cluster 0: encoder, cluster 1: decoder).
// 800 threads: warp 0 = dedicated gate warp, warps 1..24 = matvec (96 rows,
// weights in registers). Matvec warps: mbar wait -> LDS/FFMA2 -> 3 shfl ->
// stage STS -> bar.arrive. Gate warp: bar.sync -> 3 stage LDS -> gates ->
// st.async.v4 push of its 32-h chunk to all 8 CTAs (tx-barrier completion).
__global__ void __launch_bounds__(800, 1) __cluster_dims__(8, 1, 1)
gru_scan(const float* __restrict__ Whh_e, const float* __restrict__ bhh_e,
         const float* __restrict__ Whh_d, const float* __restrict__ bhh_d,
         float* __restrict__ out)
{
    __shared__ __align__(16) float hbuf[2][Hh];    // double-buffered h
    __shared__ __align__(16) float stage[96];      // fully-reduced gh rows
    __shared__ __align__(16) float gsc[32];        // gate-warp pack buffer
    __shared__ __align__(8)  unsigned long long mb[2];

    const int which = blockIdx.x >> 3;      // 0 = encoder, 1 = decoder
    const int crank = blockIdx.x & 7;       // rank within cluster
    const float* __restrict__ Whh = which ? Whh_d : Whh_e;
    const float* __restrict__ bhh = which ? bhh_d : bhh_e;
    const float* __restrict__ gi  = which ? g_gi_dec : g_gi_enc;
    float* __restrict__ out_enc = out;                    // (240, 256)
    float* __restrict__ out_dec = out + (size_t)TIN * Hh; // (128, 30, 256)
    const int L = which ? DEC_L : ENC_L;

    const int tid = threadIdx.x;
    const int w = tid >> 5, lane = tid & 31;

    const uint32_t mb_base = (uint32_t)__cvta_generic_to_shared(&mb[0]);
    const uint32_t hb_base = (uint32_t)__cvta_generic_to_shared(&hbuf[0][0]);

    // ---- matvec-warp state (w in 1..24) ----
    const int mw = w - 1;
    const int kc = lane >> 2;        // k-chunk 0..7 (32 floats each)
    const int rl = lane & 3;         // row-in-group
    const int l  = 4 * mw + rl;      // local row 0..95
    const int g  = l >> 5, j = l & 31;
    const int R  = g * 256 + crank * 32 + j;   // global gh row

    // weight slice in registers, ROTATED subchunk order so the matching h
    // reads are smem-bank-conflict-free across the warp's 8 kc groups.
    u64t wreg[16];
    int rot[8];
    if (w > 0) {
        const ulonglong2* wp =
            (const ulonglong2*)(Whh + (size_t)R * Hh + kc * 32);
#pragma unroll
        for (int i = 0; i < 8; i++) {
            const int c = (i + kc) & 7;
            ulonglong2 v = wp[c];
            wreg[2 * i]     = v.x;
            wreg[2 * i + 1] = v.y;
            rot[i] = c * 16;       // byte offset of 16B subchunk c
        }
    }

    // ---- gate-warp state (w == 0) ----
    float bhn = 0.f, hprev = 0.f;
    const float* gp = gi + crank * 32 + lane;
    float g0a = 0.f, g0b = 0.f, g0c = 0.f;   // gi for step s
    float g1a = 0.f, g1b = 0.f, g1c = 0.f;   // gi for step s+1
    uint32_t dpeer = 0;                      // peer-window delta for my rank
    if (w == 0) {
        bhn = bhh[512 + crank * 32 + lane];
        g0a = __ldg(gp);     g0b = __ldg(gp + 256);     g0c = __ldg(gp + 512);
        const float* q1 = gp + G3;
        g1a = __ldg(q1);     g1b = __ldg(q1 + 256);     g1c = __ldg(q1 + 512);
        const uint32_t rank = (uint32_t)(lane >> 2);
        dpeer = mapa_u32(hb_base, rank) - hb_base;
    }

    if (tid < Hh) hbuf[0][tid] = 0.f;
    if (tid == 0) {
        mbar_init(mb_base, 1);
        mbar_init(mb_base + 8, 1);
        // arm phase 0 of both barriers (h_1 -> mb[1], h_2 -> mb[0])
        mbar_expect_tx(mb_base, 1024);
        mbar_expect_tx(mb_base + 8, 1024);
        asm volatile("fence.mbarrier_init.release.cluster;" ::: "memory");
    }
    __syncthreads();
    // all CTAs' barriers initialized+armed before any st.async traffic
    asm volatile("barrier.cluster.arrive.aligned;" ::: "memory");
    asm volatile("barrier.cluster.wait.aligned;" ::: "memory");

    if (w > 0) {
        // ================= matvec warps =================
        for (int s = 0; s < L; s++) {
            const int cur = s & 1;
            if (s > 0) {
                const uint32_t a = mb_base + 8u * (uint32_t)cur;
                mbar_wait(a, (uint32_t)(((s >> 1) + (cur ^ 1)) & 1));
                // re-arm for this barrier's next phase; ordered before the
                // next remote writes by the arrive->gate-push->peer-wait chain
                if (tid == 32) mbar_expect_tx(a, 1024);
            }
            // dot(Whh[R, kc*32..+32), h[kc*32..+32)), rotated order
            const char* hbase = (const char*)&hbuf[cur][kc * 32];
            u64t p0 = 0ull, p1 = 0ull, p2 = 0ull, p3 = 0ull;
#pragma unroll
            for (int i = 0; i < 8; i++) {
                ulonglong2 hv = *(const ulonglong2*)(hbase + rot[i]);
                if (i & 1) {
                    p2 = ffma2(wreg[2 * i],     hv.x, p2);
                    p3 = ffma2(wreg[2 * i + 1], hv.y, p3);
                } else {
                    p0 = ffma2(wreg[2 * i],     hv.x, p0);
                    p1 = ffma2(wreg[2 * i + 1], hv.y, p1);
                }
            }
            float v = sumpair(fadd2(fadd2(p0, p1), fadd2(p2, p3)));
            v += __shfl_xor_sync(0xffffffffu, v, 4);
            v += __shfl_xor_sync(0xffffffffu, v, 8);
            v += __shfl_xor_sync(0xffffffffu, v, 16);
            if (lane < 4) stage[4 * mw + lane] = v;
            asm volatile("bar.arrive 1, 800;" ::: "memory");
        }
    } else {
        // ================= gate warp =================
        const uint32_t rank_mb0 = mb_base + dpeer;           // peer mb[0]
        const int sub = lane & 3;
        const uint32_t dst0 =
            hb_base + dpeer + (uint32_t)(crank * 128 + sub * 16);
        for (int s = 0; s < L; s++) {
            const int nxt = (s & 1) ^ 1;

            // prefetch gi for step s+2 (independent of h)
            float ta = 0.f, tb = 0.f, tc = 0.f;
            if (s + 2 < L) {
                const float* q = gp + (size_t)(s + 2) * G3;
                ta = __ldg(q); tb = __ldg(q + 256); tc = __ldg(q + 512);
            }

            // wait for all 24 matvec warps' stage stores of step s
            asm volatile("bar.sync 1, 800;" ::: "memory");

            const float sr = stage[lane];
            const float sz = stage[32 + lane];
            const float sn = stage[64 + lane] + bhn;
            const float r = sigmoid_fast(g0a + sr);
            const float z = sigmoid_fast(g0b + sz);
            const float n = tanh_fast(g0c + r * sn);
            const float hnew = n + z * (hprev - n);
            hprev = hnew;

            if (s + 1 < L) {
                gsc[lane] = hnew;
                __syncwarp();
                const float4 va = ((const float4*)gsc)[sub];
                const float4 vb = ((const float4*)gsc)[sub + 4];
                const uint32_t rm = rank_mb0 + 8u * (uint32_t)nxt;
                const uint32_t dst = dst0 + (uint32_t)(nxt * 1024);
                st_async_v4(dst, va, rm);
                st_async_v4(dst + 64, vb, rm);
            }

            if (which) {
                const int b = s & 127, t = s >> 7;
                out_dec[((size_t)b * TOUT + t) * Hh + crank * 32 + lane] = hnew;
            } else if ((s & 127) == 127) {
                const int t = s >> 7;
                out_enc[(size_t)t * Hh + crank * 32 + lane] = hnew;
            }
            g0a = g1a; g0b = g1b; g0c = g1c;
            g1a = ta;  g1b = tb;  g1c = tc;
        }
    }

    // don't exit while peers' st.async traffic targeting this CTA is in flight
    asm volatile("barrier.cluster.arrive.aligned;" ::: "memory");
    asm volatile("barrier.cluster.wait.aligned;" ::: "memory");
}

extern "C" void kernel_launch(void* const* d_in, const int* in_sizes, int n_in,
                              void* d_out, int out_size) {
    const float* x        = (const float*)d_in[0];
    const float* W_ih_enc = (const float*)d_in[1];
    const float* W_hh_enc = (const float*)d_in[2];
    const float* b_ih_enc = (const float*)d_in[3];
    const float* b_hh_enc = (const float*)d_in[4];
    const float* W_ih_dec = (const float*)d_in[5];
    const float* W_hh_dec = (const float*)d_in[6];
    const float* b_ih_dec = (const float*)d_in[7];
    const float* b_hh_dec = (const float*)d_in[8];
    float* out = (float*)d_out;

    // 1) precompute input gates (encoder stride 1 + decoder stride 8, fused)
    gi_gemm<<<dim3(G3 / 64, ENC_YBLK + DEC_YBLK), 256>>>(
        x, W_ih_enc, b_ih_enc, b_hh_enc, W_ih_dec, b_ih_dec, b_hh_dec);

    // 2) sequential scans: 2 clusters of 8 CTAs (encoder + decoder concurrent)
    gru_scan<<<16, 800>>>(W_hh_enc, b_hh_enc, W_hh_dec, b_hh_dec, out);
}

// round 6
// speedup vs baseline: 8.0264x; 1.0835x over previous
#include <cuda_runtime.h>
#include <cstdint>

#define Bsz   128
#define TIN   240
#define TOUT  30
#define Dd    128
#define Hh    256
#define G3    768
#define ENC_L (TIN*Bsz)   /* 30720 */
#define DEC_L (TOUT*Bsz)  /* 3840  */
#define ENC_YBLK (ENC_L/64)   /* 480 */
#define DEC_YBLK (DEC_L/64)   /* 60  */

// scratch: precomputed gi = x_seq @ Wih^T + (bih + bhh[r,z gates])
__device__ float g_gi_enc[(size_t)ENC_L * G3];   // ~94 MB
__device__ float g_gi_dec[(size_t)DEC_L * G3];   // ~12 MB

typedef unsigned long long u64t;

__device__ __forceinline__ u64t ffma2(u64t a, u64t b, u64t c) {
    u64t d;
    asm("fma.rn.f32x2 %0, %1, %2, %3;" : "=l"(d) : "l"(a), "l"(b), "l"(c));
    return d;
}
__device__ __forceinline__ u64t fadd2(u64t a, u64t b) {
    u64t d;
    asm("add.rn.f32x2 %0, %1, %2;" : "=l"(d) : "l"(a), "l"(b));
    return d;
}
__device__ __forceinline__ float sumpair(u64t a) {
    float x, y;
    asm("mov.b64 {%0, %1}, %2;" : "=f"(x), "=f"(y) : "l"(a));
    return x + y;
}
__device__ __forceinline__ float tanh_fast(float x) {
    float y;
    asm("tanh.approx.f32 %0, %1;" : "=f"(y) : "f"(x));
    return y;
}
__device__ __forceinline__ float sigmoid_fast(float x) {
    return fmaf(0.5f, tanh_fast(0.5f * x), 0.5f);
}
__device__ __forceinline__ uint32_t mapa_u32(uint32_t a, uint32_t rank) {
    uint32_t d;
    asm("mapa.shared::cluster.u32 %0, %1, %2;" : "=r"(d) : "r"(a), "r"(rank));
    return d;
}
__device__ __forceinline__ void mbar_init(uint32_t a, uint32_t cnt) {
    asm volatile("mbarrier.init.shared.b64 [%0], %1;" :: "r"(a), "r"(cnt) : "memory");
}
__device__ __forceinline__ void mbar_expect_tx(uint32_t a, uint32_t bytes) {
    asm volatile("mbarrier.arrive.expect_tx.shared.b64 _, [%0], %1;"
                 :: "r"(a), "r"(bytes) : "memory");
}
// local poll, CTA-scope acquire (NO cluster-scope fence in the loop)
__device__ __forceinline__ void mbar_wait(uint32_t a, uint32_t parity) {
    asm volatile(
        "{\n\t.reg .pred P;\n\t"
        "WL%=:\n\t"
        "mbarrier.try_wait.parity.acquire.cta.shared::cta.b64 P, [%0], %1, 0x989680;\n\t"
        "@P bra.uni WD%=;\n\t"
        "bra.uni WL%=;\n\t"
        "WD%=:\n\t}"
        :: "r"(a), "r"(parity) : "memory");
}
// scalar 4B store to a cluster peer's smem; feeds peer's mbarrier tx count
__device__ __forceinline__ void st_async_b32(uint32_t ra, uint32_t v, uint32_t rmbar) {
    asm volatile(
        "st.async.weak.shared::cluster.mbarrier::complete_tx::bytes.b32 "
        "[%0], %1, [%2];"
        :: "r"(ra), "r"(v), "r"(rmbar) : "memory");
}

// ===================== Kernel 1: gi GEMM (enc + dec fused) =====================
__global__ void __launch_bounds__(256) gi_gemm(
    const float* __restrict__ X,
    const float* __restrict__ Wih_e, const float* __restrict__ bih_e,
    const float* __restrict__ bhh_e,
    const float* __restrict__ Wih_d, const float* __restrict__ bih_d,
    const float* __restrict__ bhh_d)
{
    const int by = blockIdx.y;
    const int which = (by >= ENC_YBLK);
    const int row0 = (which ? (by - ENC_YBLK) : by) * 64;
    const int tstride = which ? 8 : 1;
    const float* __restrict__ Wih = which ? Wih_d : Wih_e;
    const float* __restrict__ bih = which ? bih_d : bih_e;
    const float* __restrict__ bhh = which ? bhh_d : bhh_e;
    float* __restrict__ Gi = which ? g_gi_dec : g_gi_enc;

    __shared__ float As[64][65];
    __shared__ float Bs[64][65];
    const int tid = threadIdx.x;
    const int tx = tid & 15, ty = tid >> 4;
    const int col0 = blockIdx.x * 64;
    float acc[4][4];
#pragma unroll
    for (int p = 0; p < 4; p++)
#pragma unroll
        for (int q = 0; q < 4; q++) acc[p][q] = 0.f;

    for (int kk = 0; kk < 128; kk += 64) {
#pragma unroll
        for (int i = 0; i < 16; i++) {
            int e = i * 256 + tid;
            int r = e >> 6, k = e & 63;
            int s = row0 + r;
            int b = s & 127, t = (s >> 7) * tstride;
            As[r][k] = X[((size_t)b * TIN + t) * 128 + kk + k];
        }
#pragma unroll
        for (int i = 0; i < 16; i++) {
            int e = i * 256 + tid;
            int c = e >> 6, k = e & 63;
            Bs[k][c] = Wih[(size_t)(col0 + c) * 128 + kk + k];
        }
        __syncthreads();
#pragma unroll 8
        for (int k = 0; k < 64; k++) {
            float a[4], b[4];
#pragma unroll
            for (int q = 0; q < 4; q++) a[q] = As[ty * 4 + q][k];
#pragma unroll
            for (int q = 0; q < 4; q++) b[q] = Bs[k][tx * 4 + q];
#pragma unroll
            for (int p = 0; p < 4; p++)
#pragma unroll
                for (int q = 0; q < 4; q++) acc[p][q] = fmaf(a[p], b[q], acc[p][q]);
        }
        __syncthreads();
    }
#pragma unroll
    for (int p = 0; p < 4; p++) {
        int s = row0 + ty * 4 + p;
#pragma unroll
        for (int q = 0; q < 4; q++) {
            int c = col0 + tx * 4 + q;
            float bias = bih[c] + (c < 512 ? bhh[c] : 0.f);
            Gi[(size_t)s * G3 + c] = acc[p][q] + bias;
        }
    }
}

// ===================== Kernel 2: sequential GRU scan =====================
// 2 clusters of 8 CTAs (cluster 0: encoder, cluster 1: decoder).
// 416 threads: warp 0 = gate warp; warps 1..12 = matvec, 8 rows each,
// 4 lanes per row (quarter q = lane>>3 covers h[q*64..+64), 64 weights in
// regs). Per step: mbar wait -> rotated LDS.128 / FFMA2 -> 2 shfl -> stage ->
// bar.arrive. Gate warp: bar.sync -> gates -> 8x coalesced 128B st.async
// pushes (one per peer CTA), completion via mbarrier tx bytes.
__global__ void __launch_bounds__(416, 1) __cluster_dims__(8, 1, 1)
gru_scan(const float* __restrict__ Whh_e, const float* __restrict__ bhh_e,
         const float* __restrict__ Whh_d, const float* __restrict__ bhh_d,
         float* __restrict__ out)
{
    __shared__ __align__(16) float hbuf[2][Hh];    // double-buffered h
    __shared__ __align__(16) float stage[96];      // fully-reduced gh rows
    __shared__ __align__(8)  unsigned long long mb[2];

    const int which = blockIdx.x >> 3;      // 0 = encoder, 1 = decoder
    const int crank = blockIdx.x & 7;       // rank within cluster
    const float* __restrict__ Whh = which ? Whh_d : Whh_e;
    const float* __restrict__ bhh = which ? bhh_d : bhh_e;
    const float* __restrict__ gi  = which ? g_gi_dec : g_gi_enc;
    float* __restrict__ out_enc = out;                    // (240, 256)
    float* __restrict__ out_dec = out + (size_t)TIN * Hh; // (128, 30, 256)
    const int L = which ? DEC_L : ENC_L;

    const int tid = threadIdx.x;
    const int w = tid >> 5, lane = tid & 31;

    const uint32_t mb_base = (uint32_t)__cvta_generic_to_shared(&mb[0]);
    const uint32_t hb_base = (uint32_t)__cvta_generic_to_shared(&hbuf[0][0]);

    // ---- matvec-warp state (w in 1..12) ----
    const int mw = w - 1;              // 0..11
    const int q  = lane >> 3;          // h-quarter 0..3 (64 floats each)
    const int rw = lane & 7;           // row-in-warp 0..7
    const int l  = 8 * mw + rw;        // local row 0..95
    const int gt = l >> 5, j = l & 31;
    const int R  = gt * 256 + crank * 32 + j;   // global gh row

    // 64-weight slice in registers, subchunk order (i + 2q) & 15 so the 4
    // quarters' 16B reads per LDS land in distinct bank-quads (conflict-free).
    u64t wreg[32];
    int rot[16];
    if (w > 0) {
        const float* wp = Whh + (size_t)R * Hh + q * 64;
#pragma unroll
        for (int i = 0; i < 16; i++) {
            const int c = (i + 2 * q) & 15;
            ulonglong2 v = *(const ulonglong2*)(wp + c * 4);
            wreg[2 * i]     = v.x;
            wreg[2 * i + 1] = v.y;
            rot[i] = c * 16;           // byte offset of 16B subchunk c
        }
    }

    // ---- gate-warp state (w == 0) ----
    float bhn = 0.f, hprev = 0.f;
    const float* gp = gi + crank * 32 + lane;
    float g0a = 0.f, g0b = 0.f, g0c = 0.f;   // gi for step s
    float g1a = 0.f, g1b = 0.f, g1c = 0.f;   // gi for step s+1
    uint32_t hdst[8], rmb[8];                // per-peer push addr / barrier
    if (w == 0) {
        bhn = bhh[512 + crank * 32 + lane];
        g0a = __ldg(gp);     g0b = __ldg(gp + 256);     g0c = __ldg(gp + 512);
        const float* q1 = gp + G3;
        g1a = __ldg(q1);     g1b = __ldg(q1 + 256);     g1c = __ldg(q1 + 512);
#pragma unroll
        for (int k = 0; k < 8; k++) {
            const uint32_t d = mapa_u32(hb_base, (uint32_t)k) - hb_base;
            hdst[k] = hb_base + d + (uint32_t)((crank * 32 + lane) * 4);
            rmb[k]  = mb_base + d;
        }
    }

    if (tid < Hh) hbuf[0][tid] = 0.f;
    if (tid == 0) {
        mbar_init(mb_base, 1);
        mbar_init(mb_base + 8, 1);
        // arm phase 0 of both barriers (h_1 -> mb[1], h_2 -> mb[0])
        mbar_expect_tx(mb_base, 1024);
        mbar_expect_tx(mb_base + 8, 1024);
        asm volatile("fence.mbarrier_init.release.cluster;" ::: "memory");
    }
    __syncthreads();
    // all CTAs' barriers initialized+armed before any st.async traffic
    asm volatile("barrier.cluster.arrive.aligned;" ::: "memory");
    asm volatile("barrier.cluster.wait.aligned;" ::: "memory");

    if (w > 0) {
        // ================= matvec warps =================
        for (int s = 0; s < L; s++) {
            const int cur = s & 1;
            if (s > 0) {
                const uint32_t a = mb_base + 8u * (uint32_t)cur;
                mbar_wait(a, (uint32_t)(((s >> 1) + (cur ^ 1)) & 1));
                // re-arm this barrier's next phase; ordered before the next
                // remote writes by the arrive -> gate-push -> peer-wait chain
                if (tid == 32) mbar_expect_tx(a, 1024);
            }
            // dot(Whh[R, q*64..+64), h[q*64..+64)), rotated subchunk order
            const char* hbase = (const char*)&hbuf[cur][q * 64];
            u64t p0 = 0ull, p1 = 0ull, p2 = 0ull, p3 = 0ull;
#pragma unroll
            for (int i = 0; i < 16; i++) {
                ulonglong2 hv = *(const ulonglong2*)(hbase + rot[i]);
                if (i & 1) {
                    p2 = ffma2(wreg[2 * i],     hv.x, p2);
                    p3 = ffma2(wreg[2 * i + 1], hv.y, p3);
                } else {
                    p0 = ffma2(wreg[2 * i],     hv.x, p0);
                    p1 = ffma2(wreg[2 * i + 1], hv.y, p1);
                }
            }
            float v = sumpair(fadd2(fadd2(p0, p1), fadd2(p2, p3)));
            v += __shfl_xor_sync(0xffffffffu, v, 8);
            v += __shfl_xor_sync(0xffffffffu, v, 16);
            if (lane < 8) stage[8 * mw + lane] = v;
            asm volatile("bar.arrive 1, 416;" ::: "memory");
        }
    } else {
        // ================= gate warp =================
        for (int s = 0; s < L; s++) {
            const int nxt = (s & 1) ^ 1;

            // prefetch gi for step s+2 (independent of h)
            float ta = 0.f, tb = 0.f, tc = 0.f;
            if (s + 2 < L) {
                const float* pq = gp + (size_t)(s + 2) * G3;
                ta = __ldg(pq); tb = __ldg(pq + 256); tc = __ldg(pq + 512);
            }

            // wait for all 12 matvec warps' stage stores of step s
            asm volatile("bar.sync 1, 416;" ::: "memory");

            const float sr = stage[lane];
            const float sz = stage[32 + lane];
            const float sn = stage[64 + lane] + bhn;
            const float r = sigmoid_fast(g0a + sr);
            const float z = sigmoid_fast(g0b + sz);
            const float n = tanh_fast(g0c + r * sn);
            const float hnew = n + z * (hprev - n);
            hprev = hnew;

            if (s + 1 < L) {
                // 8 coalesced 128B pushes, one per peer CTA
                const uint32_t hbits = __float_as_uint(hnew);
                const uint32_t doff = (uint32_t)(nxt * 1024);
                const uint32_t moff = (uint32_t)(nxt * 8);
#pragma unroll
                for (int k = 0; k < 8; k++)
                    st_async_b32(hdst[k] + doff, hbits, rmb[k] + moff);
            }

            if (which) {
                const int b = s & 127, t = s >> 7;
                out_dec[((size_t)b * TOUT + t) * Hh + crank * 32 + lane] = hnew;
            } else if ((s & 127) == 127) {
                const int t = s >> 7;
                out_enc[(size_t)t * Hh + crank * 32 + lane] = hnew;
            }
            g0a = g1a; g0b = g1b; g0c = g1c;
            g1a = ta;  g1b = tb;  g1c = tc;
        }
    }

    // don't exit while peers' st.async traffic targeting this CTA is in flight
    asm volatile("barrier.cluster.arrive.aligned;" ::: "memory");
    asm volatile("barrier.cluster.wait.aligned;" ::: "memory");
}

extern "C" void kernel_launch(void* const* d_in, const int* in_sizes, int n_in,
                              void* d_out, int out_size) {
    const float* x        = (const float*)d_in[0];
    const float* W_ih_enc = (const float*)d_in[1];
    const float* W_hh_enc = (const float*)d_in[2];
    const float* b_ih_enc = (const float*)d_in[3];
    const float* b_hh_enc = (const float*)d_in[4];
    const float* W_ih_dec = (const float*)d_in[5];
    const float* W_hh_dec = (const float*)d_in[6];
    const float* b_ih_dec = (const float*)d_in[7];
    const float* b_hh_dec = (const float*)d_in[8];
    float* out = (float*)d_out;

    // 1) precompute input gates (encoder stride 1 + decoder stride 8, fused)
    gi_gemm<<<dim3(G3 / 64, ENC_YBLK + DEC_YBLK), 256>>>(
        x, W_ih_enc, b_ih_enc, b_hh_enc, W_ih_dec, b_ih_dec, b_hh_dec);

    // 2) sequential scans: 2 clusters of 8 CTAs (encoder + decoder concurrent)
    gru_scan<<<16, 416>>>(W_hh_enc, b_hh_enc, W_hh_dec, b_hh_dec, out);
}